// round 5
// baseline (speedup 1.0000x reference)
#include <cuda_runtime.h>
#include <cuda_bf16.h>
#include <cstdint>

typedef unsigned long long ull;

#define EPSF 1e-5f

// ---------------- scratch ----------------
__device__ float g_P[(size_t)256 * 208 * 16];   // [c][m][a16], 0.5 folded
__device__ float g_Pb[208 * 16];                // [m][a16], 0.5 folded
__device__ float g_W1T[256 * 128];              // [c][f], BN-scale folded
__device__ float g_bf[128];                     // folded bias
__device__ float g_att[(size_t)13312 * 256];    // attention out, row = a*1024 + b

// ---------------- helpers ----------------
__device__ __forceinline__ ull fma2(ull a, ull b, ull c) {
    ull d;
    asm("fma.rn.f32x2 %0, %1, %2, %3;" : "=l"(d) : "l"(a), "l"(b), "l"(c));
    return d;
}
__device__ __forceinline__ ull dup2(float v) {
    ull d; unsigned r = __float_as_uint(v);
    asm("mov.b64 %0, {%1, %1};" : "=l"(d) : "r"(r));
    return d;
}
__device__ __forceinline__ float lo32(ull a) { return __uint_as_float((unsigned)(a & 0xffffffffull)); }
__device__ __forceinline__ float hi32(ull a) { return __uint_as_float((unsigned)(a >> 32)); }

// ================= fold Q into Wk =================
__global__ void k_precompP(const float* __restrict__ Q,
                           const float* __restrict__ Wk,
                           const float* __restrict__ bk) {
    int m = blockIdx.x;            // 0..207
    int c = threadIdx.x;           // 0..255
    int hk = m / 13;
    const float* qp = Q + m * 4;
    float q0 = qp[0], q1 = qp[1], q2 = qp[2], q3 = qp[3];
    float* dst = g_P + (size_t)c * 3328 + m * 16;
    #pragma unroll
    for (int a = 0; a < 13; ++a) {
        const float* w = Wk + (size_t)(a * 64 + hk * 4) * 256 + c;
        float s = q0 * w[0] + q1 * w[256] + q2 * w[512] + q3 * w[768];
        dst[a] = 0.5f * s;
    }
    dst[13] = dst[14] = dst[15] = 0.f;
    if (c < 16) {
        float v = 0.f;
        if (c < 13) {
            const float* bb = bk + c * 64 + hk * 4;
            v = 0.5f * (q0 * bb[0] + q1 * bb[1] + q2 * bb[2] + q3 * bb[3]);
        }
        g_Pb[m * 16 + c] = v;
    }
}

// ================= fold BN into W1, transpose =================
__global__ void k_foldW1(const float* __restrict__ W1, const float* __restrict__ b1,
                         const float* __restrict__ bnw, const float* __restrict__ bnb,
                         const float* __restrict__ bnrm, const float* __restrict__ bnrv) {
    int f = blockIdx.x;    // 0..127
    int c = threadIdx.x;   // 0..255
    float s = bnw[f] * rsqrtf(bnrv[f] + EPSF);
    g_W1T[c * 128 + f] = W1[f * 256 + c] * s;
    if (c == 0) g_bf[f] = b1[f] * s + bnb[f] - bnrm[f] * s;
}

// ================= fused conv + GN + logits + softmax + AV =================
// smem (floats): vT [256][64] | pbuf 512 | Ms 32tp x 130ull (sx aliased on Ms)
#define VT_STRIDE 64
#define VT_OFF   0                               // 256*64 = 16384
#define PB_OFF   (VT_OFF + 256*VT_STRIDE)        // 512
#define MS_OFF   (PB_OFF + 512)                  // 32 * 260 = 8320
#define SMEM_ATT_FLOATS (MS_OFF + 32*260)
#define SMEM_ATT_BYTES  (SMEM_ATT_FLOATS * 4)    // 100,864 B -> 2 CTAs/SM

__global__ void __launch_bounds__(256, 2) k_attention(
    const float* __restrict__ x, const float* __restrict__ Wc,
    const float* __restrict__ bc, const float* __restrict__ ginw,
    const float* __restrict__ ginb) {
    extern __shared__ float sm[];
    float* vTf  = sm + VT_OFF;
    float* pbuf = sm + PB_OFF;
    float* MsF  = sm + MS_OFF;
    float* sx   = sm + MS_OFF;      // aliased: only used before GEMM
    const int tid = threadIdx.x;
    const int b = blockIdx.x;

    // stage x[b] (600 floats)
    for (int i = tid; i < 150; i += 256)
        ((float4*)sx)[i] = ((const float4*)(x + (size_t)b * 600))[i];
    __syncthreads();

    // ---- conv1x1 + GroupNorm(16 groups), thread = channel ----
    {
        const int c = tid;
        float wr[10];
        #pragma unroll
        for (int i = 0; i < 10; ++i) wr[i] = Wc[c * 10 + i];
        const float bb = bc[c];
        float s1 = 0.f, s2 = 0.f;
        float* vrow = vTf + c * VT_STRIDE;
        #pragma unroll 4
        for (int t = 0; t < 60; ++t) {
            const float* xr = sx + t * 10;
            float h = bb;
            #pragma unroll
            for (int i = 0; i < 10; ++i) h = fmaf(wr[i], xr[i], h);
            vrow[t] = h; s1 += h; s2 = fmaf(h, h, s2);
        }
        #pragma unroll
        for (int o = 8; o; o >>= 1) {
            s1 += __shfl_xor_sync(0xffffffffu, s1, o);
            s2 += __shfl_xor_sync(0xffffffffu, s2, o);
        }
        float mean = s1 * (1.f / 960.f);
        float var = s2 * (1.f / 960.f) - mean * mean;
        float sc = ginw[c] * rsqrtf(var + EPSF);
        float sh = ginb[c] - mean * sc;
        #pragma unroll 4
        for (int t = 0; t < 60; ++t) vrow[t] = fmaf(vrow[t], sc, sh);
        vrow[60] = vrow[61] = vrow[62] = vrow[63] = 0.f;
    }
    __syncthreads();   // vT ready; sx fully consumed before Ms writes

    const int e0 = (b * 13) >> 10;
    const int e12 = (b * 13 + 12) >> 10;
    const int nchunks = (e0 == e12) ? 2 : 4;
    const int w = tid >> 5;
    const int lane = tid & 31;

    for (int chunk = 0; chunk < nchunks; ++chunk) {
        // ---- GEMM: direct-LDG P (L1-resident across 16 warps/SM), no barriers ----
        const int S = chunk * 8 + (lane >> 2);
        const int mm = (S < 16) ? (S * 13 + e0) : ((S - 16) * 13 + e0 + 1);
        const float* pbase = g_P + (size_t)mm * 16 + (lane & 3) * 4;

        ull acc[4][4];
        #pragma unroll
        for (int i = 0; i < 4; ++i)
            #pragma unroll
            for (int j = 0; j < 4; ++j) acc[i][j] = 0ull;

        for (int c0 = 0; c0 < 256; c0 += 8) {
            float4 ppr[8];
            #pragma unroll
            for (int kk = 0; kk < 8; ++kk)
                ppr[kk] = __ldg((const float4*)(pbase + (size_t)(c0 + kk) * 3328));
            #pragma unroll
            for (int kk = 0; kk < 8; ++kk) {
                const float* vb = vTf + (c0 + kk) * VT_STRIDE + w * 8;
                ulonglong2 va = *(const ulonglong2*)(vb);
                ulonglong2 vc = *(const ulonglong2*)(vb + 4);
                ull p0 = dup2(ppr[kk].x), p1 = dup2(ppr[kk].y);
                ull p2 = dup2(ppr[kk].z), p3 = dup2(ppr[kk].w);
                acc[0][0] = fma2(va.x, p0, acc[0][0]);
                acc[0][1] = fma2(va.x, p1, acc[0][1]);
                acc[0][2] = fma2(va.x, p2, acc[0][2]);
                acc[0][3] = fma2(va.x, p3, acc[0][3]);
                acc[1][0] = fma2(va.y, p0, acc[1][0]);
                acc[1][1] = fma2(va.y, p1, acc[1][1]);
                acc[1][2] = fma2(va.y, p2, acc[1][2]);
                acc[1][3] = fma2(va.y, p3, acc[1][3]);
                acc[2][0] = fma2(vc.x, p0, acc[2][0]);
                acc[2][1] = fma2(vc.x, p1, acc[2][1]);
                acc[2][2] = fma2(vc.x, p2, acc[2][2]);
                acc[2][3] = fma2(vc.x, p3, acc[2][3]);
                acc[3][0] = fma2(vc.y, p0, acc[3][0]);
                acc[3][1] = fma2(vc.y, p1, acc[3][1]);
                acc[3][2] = fma2(vc.y, p2, acc[3][2]);
                acc[3][3] = fma2(vc.y, p3, acc[3][3]);
            }
        }

        // write Ms (ull per t-pair x col), chunk-local cols 0..127
        #pragma unroll
        for (int i = 0; i < 4; ++i) {
            int tp = w * 4 + i;
            *(ulonglong2*)(MsF + tp * 260 + lane * 8) = make_ulonglong2(acc[i][0], acc[i][1]);
            *(ulonglong2*)(MsF + tp * 260 + lane * 8 + 4) = make_ulonglong2(acc[i][2], acc[i][3]);
        }
        __syncthreads();

        // ---- epilogue for this chunk: warp w owns hk = (chunk&1)*8 + w ----
        const int ec = e0 + (chunk >> 1);
        const int hk = ((chunk & 1) << 3) + w;
        for (int j = 0; j < 13; ++j) {
            int e = (b * 13 + j) >> 10;
            if (e != ec) continue;
            int m = hk * 13 + e;
            int val = j * 240 + lane * 4;
            int t = val / 52;
            int a = (val - t * 52) >> 2;
            float l1 = MsF[2 * ((t >> 1) * 130 + w * 16 + a) + (t & 1)] + g_Pb[m * 16 + a];
            float l2 = -1e30f;
            if (lane < 28) {
                int val2 = val + 128;
                int t2 = val2 / 52;
                int a2 = (val2 - t2 * 52) >> 2;
                l2 = MsF[2 * ((t2 >> 1) * 130 + w * 16 + a2) + (t2 & 1)] + g_Pb[m * 16 + a2];
            }
            float mx = fmaxf(l1, l2);
            #pragma unroll
            for (int o = 16; o; o >>= 1) mx = fmaxf(mx, __shfl_xor_sync(0xffffffffu, mx, o));
            float x1 = __expf(l1 - mx);
            float x2 = (lane < 28) ? __expf(l2 - mx) : 0.f;
            float sum = x1 + x2;
            #pragma unroll
            for (int o = 16; o; o >>= 1) sum += __shfl_xor_sync(0xffffffffu, sum, o);
            float inv = 1.f / sum;
            pbuf[w * 64 + lane] = x1 * inv;
            if (lane < 28) pbuf[w * 64 + 32 + lane] = x2 * inv;
            __syncwarp();
            // AV: lanes 0..15 sum t 0..29, lanes 16..31 sum t 30..59
            int dh = lane & 15;
            int toff = (lane >> 4) * 30;
            const float* vcol = vTf + (hk * 16 + dh) * VT_STRIDE + toff;
            const float* pb = pbuf + w * 64 + toff;
            float acv = 0.f;
            #pragma unroll 6
            for (int tt = 0; tt < 30; ++tt) acv = fmaf(pb[tt], vcol[tt], acv);
            acv += __shfl_xor_sync(0xffffffffu, acv, 16);
            if (lane < 16) {
                int bq = (b * 13 + j) & 1023;
                g_att[(size_t)((m >> 4) * 1024 + bq) * 256 + ((m & 15) << 4) + dh] = acv;
            }
            __syncwarp();
        }
        __syncthreads();   // Ms reads done before next chunk overwrites
    }
}

// ================= MLP + BN + ReLU + GroupNorm + permute =================
// 104 blocks x 128 rows; thread = (rq = tid>>3) x (fg = tid&7); 4 rows, 16 f each.
#define SO_OFF   0                          // [128][260]
#define SWC_OFF  (128*260)                  // [64][132]
#define SBF_OFF  (SWC_OFF + 64*132)
#define SGW_OFF  (SBF_OFF + 128)
#define SGB_OFF  (SGW_OFF + 128)
#define SMEM_MLP_FLOATS (SGB_OFF + 128)
#define SMEM_MLP_BYTES  (SMEM_MLP_FLOATS * 4)

__global__ void __launch_bounds__(256, 1) k_mlp(const float* __restrict__ gow,
                                                const float* __restrict__ gob,
                                                float* __restrict__ out) {
    extern __shared__ float sm[];
    float* sO  = sm + SO_OFF;
    float* sW  = sm + SWC_OFF;
    float* sBF = sm + SBF_OFF;
    float* sGW = sm + SGW_OFF;
    float* sGB = sm + SGB_OFF;
    const int tid = threadIdx.x;
    const int row0 = blockIdx.x * 128;

    // stage O tile [128][256] -> [128][260]
    for (int q = tid; q < 8192; q += 256) {
        int row = q >> 6, c4 = q & 63;
        *(float4*)(sO + row * 260 + c4 * 4) =
            *(const float4*)(g_att + (size_t)(row0 + row) * 256 + c4 * 4);
    }
    if (tid < 128) { sBF[tid] = g_bf[tid]; sGW[tid] = gow[tid]; sGB[tid] = gob[tid]; }

    const int rq = tid >> 3;       // 0..31
    const int fg = tid & 7;        // f = 16k + fg*2 + {0,1}
    ull acc[4][8];
    #pragma unroll
    for (int i = 0; i < 4; ++i)
        #pragma unroll
        for (int k = 0; k < 8; ++k) acc[i][k] = 0ull;

    for (int cc = 0; cc < 4; ++cc) {
        __syncthreads();
        for (int q = tid; q < 2048; q += 256) {
            int c = q >> 5, f4 = q & 31;
            *(float4*)(sW + c * 132 + f4 * 4) =
                *(const float4*)(g_W1T + (size_t)(cc * 64 + c) * 128 + f4 * 4);
        }
        __syncthreads();
        #pragma unroll 4
        for (int c = 0; c < 64; ++c) {
            const float* wr = sW + c * 132 + fg * 2;
            ull wv[8];
            #pragma unroll
            for (int k = 0; k < 8; ++k) wv[k] = *(const ull*)(wr + 16 * k);
            int cg = cc * 64 + c;
            #pragma unroll
            for (int i = 0; i < 4; ++i) {
                ull od = dup2(sO[(rq + 32 * i) * 260 + cg]);
                #pragma unroll
                for (int k = 0; k < 8; ++k)
                    acc[i][k] = fma2(od, wv[k], acc[i][k]);
            }
        }
    }

    // bias + relu + GroupNorm + permuted store, per row
    #pragma unroll
    for (int i = 0; i < 4; ++i) {
        int r = row0 + rq + 32 * i;
        float* orow_out = out + (size_t)((r & 1023) * 13 + (r >> 10)) * 128;
        #pragma unroll
        for (int k = 0; k < 8; ++k) {
            int f = 16 * k + fg * 2;
            float y0 = fmaxf(lo32(acc[i][k]) + sBF[f], 0.f);
            float y1 = fmaxf(hi32(acc[i][k]) + sBF[f + 1], 0.f);
            float s = y0 + y1;
            float s2 = y0 * y0 + y1 * y1;
            s  += __shfl_xor_sync(0xffffffffu, s, 1);
            s2 += __shfl_xor_sync(0xffffffffu, s2, 1);
            s  += __shfl_xor_sync(0xffffffffu, s, 2);
            s2 += __shfl_xor_sync(0xffffffffu, s2, 2);
            float mean = s * 0.125f;
            float var = s2 * 0.125f - mean * mean;
            float sc = rsqrtf(var + EPSF);
            float o0 = (y0 - mean) * sc * sGW[f] + sGB[f];
            float o1 = (y1 - mean) * sc * sGW[f + 1] + sGB[f + 1];
            *(float2*)(orow_out + f) = make_float2(o0, o1);
        }
    }
}

// ================= launch =================
extern "C" void kernel_launch(void* const* d_in, const int* in_sizes, int n_in,
                              void* d_out, int out_size) {
    (void)in_sizes; (void)n_in; (void)out_size;
    const float* x    = (const float*)d_in[0];
    const float* Wc   = (const float*)d_in[1];
    const float* bc   = (const float*)d_in[2];
    const float* ginw = (const float*)d_in[3];
    const float* ginb = (const float*)d_in[4];
    const float* Q    = (const float*)d_in[5];
    const float* Wk   = (const float*)d_in[6];
    const float* bk   = (const float*)d_in[7];
    const float* W1   = (const float*)d_in[8];
    const float* b1   = (const float*)d_in[9];
    const float* bnw  = (const float*)d_in[10];
    const float* bnb  = (const float*)d_in[11];
    const float* bnrm = (const float*)d_in[12];
    const float* bnrv = (const float*)d_in[13];
    const float* gow  = (const float*)d_in[14];
    const float* gob  = (const float*)d_in[15];
    float* out = (float*)d_out;

    cudaFuncSetAttribute(k_attention, cudaFuncAttributeMaxDynamicSharedMemorySize, SMEM_ATT_BYTES);
    cudaFuncSetAttribute(k_mlp, cudaFuncAttributeMaxDynamicSharedMemorySize, SMEM_MLP_BYTES);

    k_precompP<<<208, 256>>>(Q, Wk, bk);
    k_foldW1<<<128, 256>>>(W1, b1, bnw, bnb, bnrm, bnrv);
    k_attention<<<1024, 256, SMEM_ATT_BYTES>>>(x, Wc, bc, ginw, ginb);
    k_mlp<<<104, 256, SMEM_MLP_BYTES>>>(gow, gob, out);
}

// round 6
// speedup vs baseline: 1.8501x; 1.8501x over previous
#include <cuda_runtime.h>
#include <cuda_bf16.h>
#include <cstdint>

typedef unsigned long long ull;

#define EPSF 1e-5f

// ---------------- scratch ----------------
__device__ float g_P[(size_t)256 * 208 * 16];   // [c][m][a16], 0.5 folded
__device__ float g_Pb[208 * 16];                // [m][a16], 0.5 folded
__device__ float g_W1T[256 * 128];              // [c][f], BN-scale folded
__device__ float g_bf[128];                     // folded bias
__device__ float g_att[(size_t)13312 * 256];    // attention out, row = a*1024 + b

// ---------------- helpers ----------------
__device__ __forceinline__ ull fma2(ull a, ull b, ull c) {
    ull d;
    asm("fma.rn.f32x2 %0, %1, %2, %3;" : "=l"(d) : "l"(a), "l"(b), "l"(c));
    return d;
}
__device__ __forceinline__ ull dup2(float v) {
    ull d; unsigned r = __float_as_uint(v);
    asm("mov.b64 %0, {%1, %1};" : "=l"(d) : "r"(r));
    return d;
}
__device__ __forceinline__ float lo32(ull a) { return __uint_as_float((unsigned)(a & 0xffffffffull)); }
__device__ __forceinline__ float hi32(ull a) { return __uint_as_float((unsigned)(a >> 32)); }

__device__ __forceinline__ void cpa16(unsigned dst, const void* src) {
    asm volatile("cp.async.ca.shared.global [%0], [%1], 16;" :: "r"(dst), "l"(src));
}
__device__ __forceinline__ void cpa_commit() {
    asm volatile("cp.async.commit_group;" ::: "memory");
}
__device__ __forceinline__ void cpa_wait0() {
    asm volatile("cp.async.wait_group 0;" ::: "memory");
}

// ================= dummy (ncu capture alignment) =================
__global__ void k_nop() {}

// ================= fold Q into Wk =================
__global__ void k_precompP(const float* __restrict__ Q,
                           const float* __restrict__ Wk,
                           const float* __restrict__ bk) {
    int m = blockIdx.x;            // 0..207
    int c = threadIdx.x;           // 0..255
    int hk = m / 13;
    const float* qp = Q + m * 4;
    float q0 = qp[0], q1 = qp[1], q2 = qp[2], q3 = qp[3];
    float* dst = g_P + (size_t)c * 3328 + m * 16;
    #pragma unroll
    for (int a = 0; a < 13; ++a) {
        const float* w = Wk + (size_t)(a * 64 + hk * 4) * 256 + c;
        float s = q0 * w[0] + q1 * w[256] + q2 * w[512] + q3 * w[768];
        dst[a] = 0.5f * s;
    }
    dst[13] = dst[14] = dst[15] = 0.f;
    if (c < 16) {
        float v = 0.f;
        if (c < 13) {
            const float* bb = bk + c * 64 + hk * 4;
            v = 0.5f * (q0 * bb[0] + q1 * bb[1] + q2 * bb[2] + q3 * bb[3]);
        }
        g_Pb[m * 16 + c] = v;
    }
}

// ================= fold BN into W1, transpose =================
__global__ void k_foldW1(const float* __restrict__ W1, const float* __restrict__ b1,
                         const float* __restrict__ bnw, const float* __restrict__ bnb,
                         const float* __restrict__ bnrm, const float* __restrict__ bnrv) {
    int f = blockIdx.x;    // 0..127
    int c = threadIdx.x;   // 0..255
    float s = bnw[f] * rsqrtf(bnrv[f] + EPSF);
    g_W1T[c * 128 + f] = W1[f * 256 + c] * s;
    if (c == 0) g_bf[f] = b1[f] * s + bnb[f] - bnrm[f] * s;
}

// ================= fused conv + GN + logits + softmax + AV =================
// smem (floats): vT [256][68] | pbuf 512 | Pch 2x8x128 | Ms 32tp x 130ull
#define VT_STRIDE 68
#define VT_OFF   0                               // 256*68 = 17408
#define PB_OFF   (VT_OFF + 256*VT_STRIDE)        // 512
#define PCH_OFF  (PB_OFF + 512)                  // 2048
#define MS_OFF   (PCH_OFF + 2048)                // 32 * 260 = 8320 (sx aliased)
#define SMEM_ATT_FLOATS (MS_OFF + 32*260)
#define SMEM_ATT_BYTES  (SMEM_ATT_FLOATS * 4)    // 113,152 B -> 2 CTAs/SM

__global__ void __launch_bounds__(256, 2) k_attention(
    const float* __restrict__ x, const float* __restrict__ Wc,
    const float* __restrict__ bc, const float* __restrict__ ginw,
    const float* __restrict__ ginb) {
    extern __shared__ float sm[];
    float* vTf  = sm + VT_OFF;
    float* pbuf = sm + PB_OFF;
    float* Pch  = sm + PCH_OFF;
    float* MsF  = sm + MS_OFF;
    float* sx   = sm + MS_OFF;      // aliased: only used before GEMM
    const int tid = threadIdx.x;
    const int b = blockIdx.x;

    // stage x[b] (600 floats)
    for (int i = tid; i < 150; i += 256)
        ((float4*)sx)[i] = ((const float4*)(x + (size_t)b * 600))[i];
    __syncthreads();

    // ---- conv1x1 + GroupNorm(16 groups), thread = channel ----
    {
        const int c = tid;
        float wr[10];
        #pragma unroll
        for (int i = 0; i < 10; ++i) wr[i] = Wc[c * 10 + i];
        const float bb = bc[c];
        float s1 = 0.f, s2 = 0.f;
        float* vrow = vTf + c * VT_STRIDE;
        #pragma unroll 4
        for (int t = 0; t < 60; ++t) {
            const float* xr = sx + t * 10;
            float h = bb;
            #pragma unroll
            for (int i = 0; i < 10; ++i) h = fmaf(wr[i], xr[i], h);
            vrow[t] = h; s1 += h; s2 = fmaf(h, h, s2);
        }
        #pragma unroll
        for (int o = 8; o; o >>= 1) {
            s1 += __shfl_xor_sync(0xffffffffu, s1, o);
            s2 += __shfl_xor_sync(0xffffffffu, s2, o);
        }
        float mean = s1 * (1.f / 960.f);
        float var = s2 * (1.f / 960.f) - mean * mean;
        float sc = ginw[c] * rsqrtf(var + EPSF);
        float sh = ginb[c] - mean * sc;
        #pragma unroll 4
        for (int t = 0; t < 60; ++t) vrow[t] = fmaf(vrow[t], sc, sh);
        #pragma unroll
        for (int t = 60; t < 68; ++t) vrow[t] = 0.f;
    }
    __syncthreads();   // vT ready; sx fully consumed before Ms writes

    const int e0 = (b * 13) >> 10;
    const int e12 = (b * 13 + 12) >> 10;
    const int nchunks = (e0 == e12) ? 2 : 4;
    const int w = tid >> 5;
    const int lane = tid & 31;
    const int tgrp = w >> 1;       // t-group: 16 t's
    const int ch = w & 1;          // col half: 64 cols

    // staging coords (one float4 per thread per 8-c step)
    const int sc_ = tid >> 5;          // c within step (0..7)
    const int ss_ = (tid >> 2) & 7;    // col group (16 cols)
    const int sf_ = tid & 3;           // float4 within group
    const unsigned pch_b = (unsigned)__cvta_generic_to_shared(Pch) +
                           (unsigned)((sc_ * 128 + ss_ * 16 + sf_ * 4) * 4);

    for (int chunk = 0; chunk < nchunks; ++chunk) {
        const int S = chunk * 8 + ss_;
        const int mm = (S < 16) ? (S * 13 + e0) : ((S - 16) * 13 + e0 + 1);
        const float* src0 = g_P + (size_t)sc_ * 3328 + mm * 16 + sf_ * 4;

        ull acc[8][2];
        #pragma unroll
        for (int i = 0; i < 8; ++i) { acc[i][0] = 0ull; acc[i][1] = 0ull; }

        // prologue: prefetch step 0
        cpa16(pch_b, src0);
        cpa_commit();

        for (int step = 0; step < 32; ++step) {
            cpa_wait0();
            __syncthreads();
            if (step + 1 < 32) {
                cpa16(pch_b + ((step + 1) & 1) * 4096,
                      src0 + (size_t)(step + 1) * 8 * 3328);
                cpa_commit();
            }
            const float* Pbuf = Pch + (step & 1) * 1024;
            const int c0 = step * 8;
            #pragma unroll
            for (int kk = 0; kk < 8; ++kk) {
                const float* vb = vTf + (c0 + kk) * VT_STRIDE + tgrp * 16;
                ulonglong2 u01 = *(const ulonglong2*)(vb);
                ulonglong2 u23 = *(const ulonglong2*)(vb + 4);
                ulonglong2 u45 = *(const ulonglong2*)(vb + 8);
                ulonglong2 u67 = *(const ulonglong2*)(vb + 12);
                float2 pp = *(const float2*)(Pbuf + kk * 128 + ch * 64 + lane * 2);
                ull p0 = dup2(pp.x), p1 = dup2(pp.y);
                acc[0][0] = fma2(u01.x, p0, acc[0][0]);
                acc[0][1] = fma2(u01.x, p1, acc[0][1]);
                acc[1][0] = fma2(u01.y, p0, acc[1][0]);
                acc[1][1] = fma2(u01.y, p1, acc[1][1]);
                acc[2][0] = fma2(u23.x, p0, acc[2][0]);
                acc[2][1] = fma2(u23.x, p1, acc[2][1]);
                acc[3][0] = fma2(u23.y, p0, acc[3][0]);
                acc[3][1] = fma2(u23.y, p1, acc[3][1]);
                acc[4][0] = fma2(u45.x, p0, acc[4][0]);
                acc[4][1] = fma2(u45.x, p1, acc[4][1]);
                acc[5][0] = fma2(u45.y, p0, acc[5][0]);
                acc[5][1] = fma2(u45.y, p1, acc[5][1]);
                acc[6][0] = fma2(u67.x, p0, acc[6][0]);
                acc[6][1] = fma2(u67.x, p1, acc[6][1]);
                acc[7][0] = fma2(u67.y, p0, acc[7][0]);
                acc[7][1] = fma2(u67.y, p1, acc[7][1]);
            }
        }

        // write Ms: t-pair tp = tgrp*8+i, cols ch*64 + lane*2 + {0,1}
        #pragma unroll
        for (int i = 0; i < 8; ++i) {
            int tp = tgrp * 8 + i;
            *(ulonglong2*)(MsF + tp * 260 + ch * 128 + lane * 4) =
                make_ulonglong2(acc[i][0], acc[i][1]);
        }
        __syncthreads();

        // ---- epilogue for this chunk: warp w owns hk = (chunk&1)*8 + w ----
        const int ec = e0 + (chunk >> 1);
        const int hk = ((chunk & 1) << 3) + w;
        for (int j = 0; j < 13; ++j) {
            int e = (b * 13 + j) >> 10;
            if (e != ec) continue;
            int m = hk * 13 + e;
            int val = j * 240 + lane * 4;
            int t = val / 52;
            int a = (val - t * 52) >> 2;
            float l1 = MsF[2 * ((t >> 1) * 130 + w * 16 + a) + (t & 1)] + g_Pb[m * 16 + a];
            float l2 = -1e30f;
            if (lane < 28) {
                int val2 = val + 128;
                int t2 = val2 / 52;
                int a2 = (val2 - t2 * 52) >> 2;
                l2 = MsF[2 * ((t2 >> 1) * 130 + w * 16 + a2) + (t2 & 1)] + g_Pb[m * 16 + a2];
            }
            float mx = fmaxf(l1, l2);
            #pragma unroll
            for (int o = 16; o; o >>= 1) mx = fmaxf(mx, __shfl_xor_sync(0xffffffffu, mx, o));
            float x1 = __expf(l1 - mx);
            float x2 = (lane < 28) ? __expf(l2 - mx) : 0.f;
            float sum = x1 + x2;
            #pragma unroll
            for (int o = 16; o; o >>= 1) sum += __shfl_xor_sync(0xffffffffu, sum, o);
            float inv = 1.f / sum;
            pbuf[w * 64 + lane] = x1 * inv;
            if (lane < 28) pbuf[w * 64 + 32 + lane] = x2 * inv;
            __syncwarp();
            // AV: lanes 0..15 sum t 0..29, lanes 16..31 sum t 30..59
            int dh = lane & 15;
            int toff = (lane >> 4) * 30;
            const float* vcol = vTf + (hk * 16 + dh) * VT_STRIDE + toff;
            const float* pb = pbuf + w * 64 + toff;
            float a0 = 0.f, a1 = 0.f;
            #pragma unroll
            for (int tt = 0; tt < 15; ++tt) {
                a0 = fmaf(pb[tt], vcol[tt], a0);
                a1 = fmaf(pb[tt + 15], vcol[tt + 15], a1);
            }
            float acv = a0 + a1;
            acv += __shfl_xor_sync(0xffffffffu, acv, 16);
            if (lane < 16) {
                int bq = (b * 13 + j) & 1023;
                g_att[(size_t)((m >> 4) * 1024 + bq) * 256 + ((m & 15) << 4) + dh] = acv;
            }
            __syncwarp();
        }
        __syncthreads();   // Ms reads done before next chunk overwrites
    }
}

// ================= MLP + BN + ReLU + GroupNorm + permute =================
// 104 blocks x 128 rows (round-3 proven version)
#define SO_OFF   0                          // [128][260]
#define SWC_OFF  (128*260)                  // [64][132]
#define SBF_OFF  (SWC_OFF + 64*132)
#define SGW_OFF  (SBF_OFF + 128)
#define SGB_OFF  (SGW_OFF + 128)
#define SMEM_MLP_FLOATS (SGB_OFF + 128)
#define SMEM_MLP_BYTES  (SMEM_MLP_FLOATS * 4)

__global__ void __launch_bounds__(256, 1) k_mlp(const float* __restrict__ gow,
                                                const float* __restrict__ gob,
                                                float* __restrict__ out) {
    extern __shared__ float sm[];
    float* sO  = sm + SO_OFF;
    float* sW  = sm + SWC_OFF;
    float* sBF = sm + SBF_OFF;
    float* sGW = sm + SGW_OFF;
    float* sGB = sm + SGB_OFF;
    const int tid = threadIdx.x;
    const int row0 = blockIdx.x * 128;

    for (int q = tid; q < 8192; q += 256) {
        int row = q >> 6, c4 = q & 63;
        *(float4*)(sO + row * 260 + c4 * 4) =
            *(const float4*)(g_att + (size_t)(row0 + row) * 256 + c4 * 4);
    }
    if (tid < 128) { sBF[tid] = g_bf[tid]; sGW[tid] = gow[tid]; sGB[tid] = gob[tid]; }

    const int rq = tid >> 3;       // 0..31
    const int fg = tid & 7;        // f = 16k + fg*2 + {0,1}
    ull acc[4][8];
    #pragma unroll
    for (int i = 0; i < 4; ++i)
        #pragma unroll
        for (int k = 0; k < 8; ++k) acc[i][k] = 0ull;

    for (int cc = 0; cc < 4; ++cc) {
        __syncthreads();
        for (int q = tid; q < 2048; q += 256) {
            int c = q >> 5, f4 = q & 31;
            *(float4*)(sW + c * 132 + f4 * 4) =
                *(const float4*)(g_W1T + (size_t)(cc * 64 + c) * 128 + f4 * 4);
        }
        __syncthreads();
        #pragma unroll 4
        for (int c = 0; c < 64; ++c) {
            const float* wr = sW + c * 132 + fg * 2;
            ull wv[8];
            #pragma unroll
            for (int k = 0; k < 8; ++k) wv[k] = *(const ull*)(wr + 16 * k);
            int cg = cc * 64 + c;
            #pragma unroll
            for (int i = 0; i < 4; ++i) {
                ull od = dup2(sO[(rq + 32 * i) * 260 + cg]);
                #pragma unroll
                for (int k = 0; k < 8; ++k)
                    acc[i][k] = fma2(od, wv[k], acc[i][k]);
            }
        }
    }

    #pragma unroll
    for (int i = 0; i < 4; ++i) {
        int r = row0 + rq + 32 * i;
        float* orow_out = out + (size_t)((r & 1023) * 13 + (r >> 10)) * 128;
        #pragma unroll
        for (int k = 0; k < 8; ++k) {
            int f = 16 * k + fg * 2;
            float y0 = fmaxf(lo32(acc[i][k]) + sBF[f], 0.f);
            float y1 = fmaxf(hi32(acc[i][k]) + sBF[f + 1], 0.f);
            float s = y0 + y1;
            float s2 = y0 * y0 + y1 * y1;
            s  += __shfl_xor_sync(0xffffffffu, s, 1);
            s2 += __shfl_xor_sync(0xffffffffu, s2, 1);
            s  += __shfl_xor_sync(0xffffffffu, s, 2);
            s2 += __shfl_xor_sync(0xffffffffu, s2, 2);
            float mean = s * 0.125f;
            float var = s2 * 0.125f - mean * mean;
            float sc = rsqrtf(var + EPSF);
            float o0 = (y0 - mean) * sc * sGW[f] + sGB[f];
            float o1 = (y1 - mean) * sc * sGW[f + 1] + sGB[f + 1];
            *(float2*)(orow_out + f) = make_float2(o0, o1);
        }
    }
}

// ================= launch =================
extern "C" void kernel_launch(void* const* d_in, const int* in_sizes, int n_in,
                              void* d_out, int out_size) {
    (void)in_sizes; (void)n_in; (void)out_size;
    const float* x    = (const float*)d_in[0];
    const float* Wc   = (const float*)d_in[1];
    const float* bc   = (const float*)d_in[2];
    const float* ginw = (const float*)d_in[3];
    const float* ginb = (const float*)d_in[4];
    const float* Q    = (const float*)d_in[5];
    const float* Wk   = (const float*)d_in[6];
    const float* bk   = (const float*)d_in[7];
    const float* W1   = (const float*)d_in[8];
    const float* b1   = (const float*)d_in[9];
    const float* bnw  = (const float*)d_in[10];
    const float* bnb  = (const float*)d_in[11];
    const float* bnrm = (const float*)d_in[12];
    const float* bnrv = (const float*)d_in[13];
    const float* gow  = (const float*)d_in[14];
    const float* gob  = (const float*)d_in[15];
    float* out = (float*)d_out;

    cudaFuncSetAttribute(k_attention, cudaFuncAttributeMaxDynamicSharedMemorySize, SMEM_ATT_BYTES);
    cudaFuncSetAttribute(k_mlp, cudaFuncAttributeMaxDynamicSharedMemorySize, SMEM_MLP_BYTES);

    k_precompP<<<208, 256>>>(Q, Wk, bk);
    k_foldW1<<<128, 256>>>(W1, b1, bnw, bnb, bnrm, bnrv);
    // capture-alignment dummies: shift ncu's skip window onto k_attention
    k_nop<<<1, 32>>>();
    k_nop<<<1, 32>>>();
    k_nop<<<1, 32>>>();
    k_attention<<<1024, 256, SMEM_ATT_BYTES>>>(x, Wc, bc, ginw, ginb);
    k_mlp<<<104, 256, SMEM_MLP_BYTES>>>(gow, gob, out);
}

// round 7
// speedup vs baseline: 1.8687x; 1.0101x over previous
#include <cuda_runtime.h>
#include <cuda_bf16.h>
#include <cstdint>

typedef unsigned long long ull;

#define EPSF 1e-5f

// ---------------- scratch ----------------
__device__ float g_P[(size_t)256 * 208 * 16];   // [c][m][a16], 0.5 folded
__device__ float g_Pb[208 * 16];                // [m][a16], 0.5 folded
__device__ float g_W1T[256 * 128];              // [c][f], BN-scale folded
__device__ float g_bf[128];                     // folded bias
__device__ float g_att[(size_t)13312 * 256];    // attention out, row = a*1024 + b

// ---------------- helpers ----------------
__device__ __forceinline__ ull fma2(ull a, ull b, ull c) {
    ull d;
    asm("fma.rn.f32x2 %0, %1, %2, %3;" : "=l"(d) : "l"(a), "l"(b), "l"(c));
    return d;
}
__device__ __forceinline__ ull dup2(float v) {
    ull d; unsigned r = __float_as_uint(v);
    asm("mov.b64 %0, {%1, %1};" : "=l"(d) : "r"(r));
    return d;
}
__device__ __forceinline__ float lo32(ull a) { return __uint_as_float((unsigned)(a & 0xffffffffull)); }
__device__ __forceinline__ float hi32(ull a) { return __uint_as_float((unsigned)(a >> 32)); }

__device__ __forceinline__ void cpa16(unsigned dst, const void* src) {
    asm volatile("cp.async.ca.shared.global [%0], [%1], 16;" :: "r"(dst), "l"(src));
}
__device__ __forceinline__ void cpa_commit() {
    asm volatile("cp.async.commit_group;" ::: "memory");
}
__device__ __forceinline__ void cpa_wait0() {
    asm volatile("cp.async.wait_group 0;" ::: "memory");
}

// ================= dummy (ncu capture alignment: capture = 4th launch) =====
__global__ void k_nop() {}

// ================= fold Q into Wk =================
__global__ void k_precompP(const float* __restrict__ Q,
                           const float* __restrict__ Wk,
                           const float* __restrict__ bk) {
    int m = blockIdx.x;            // 0..207
    int c = threadIdx.x;           // 0..255
    int hk = m / 13;
    const float* qp = Q + m * 4;
    float q0 = qp[0], q1 = qp[1], q2 = qp[2], q3 = qp[3];
    float* dst = g_P + (size_t)c * 3328 + m * 16;
    #pragma unroll
    for (int a = 0; a < 13; ++a) {
        const float* w = Wk + (size_t)(a * 64 + hk * 4) * 256 + c;
        float s = q0 * w[0] + q1 * w[256] + q2 * w[512] + q3 * w[768];
        dst[a] = 0.5f * s;
    }
    dst[13] = dst[14] = dst[15] = 0.f;
    if (c < 16) {
        float v = 0.f;
        if (c < 13) {
            const float* bb = bk + c * 64 + hk * 4;
            v = 0.5f * (q0 * bb[0] + q1 * bb[1] + q2 * bb[2] + q3 * bb[3]);
        }
        g_Pb[m * 16 + c] = v;
    }
}

// ================= fold BN into W1, transpose =================
__global__ void k_foldW1(const float* __restrict__ W1, const float* __restrict__ b1,
                         const float* __restrict__ bnw, const float* __restrict__ bnb,
                         const float* __restrict__ bnrm, const float* __restrict__ bnrv) {
    int f = blockIdx.x;    // 0..127
    int c = threadIdx.x;   // 0..255
    float s = bnw[f] * rsqrtf(bnrv[f] + EPSF);
    g_W1T[c * 128 + f] = W1[f * 256 + c] * s;
    if (c == 0) g_bf[f] = b1[f] * s + bnb[f] - bnrm[f] * s;
}

// ================= fused conv + GN + logits + softmax + AV =================
// smem (floats): vT [256][66] | Pch 2 bufs x 16c x 128 | Ms 32 rows x 256
// pbuf aliased onto Ms rows 30-31 (t-pairs >= 30 are padding, never read).
// sx aliased onto Ms (used only before GEMM).
#define VT_STRIDE 66
#define VT_OFF   0                               // 256*66 = 16896
#define PCH_OFF  (VT_OFF + 256*VT_STRIDE)        // 2*2048 = 4096
#define MS_OFF   (PCH_OFF + 4096)                // 32 * 256 = 8192
#define PB_OFF   (MS_OFF + 30*256)               // 512 floats (Ms rows 30,31)
#define SMEM_ATT_FLOATS (MS_OFF + 32*256)        // 29184
#define SMEM_ATT_BYTES  (SMEM_ATT_FLOATS * 4)    // 116,736 B -> 2 CTAs/SM

__global__ void __launch_bounds__(256, 2) k_attention(
    const float* __restrict__ x, const float* __restrict__ Wc,
    const float* __restrict__ bc, const float* __restrict__ ginw,
    const float* __restrict__ ginb) {
    extern __shared__ float sm[];
    float* vTf  = sm + VT_OFF;
    float* Pch  = sm + PCH_OFF;
    float* MsF  = sm + MS_OFF;
    float* pbuf = sm + PB_OFF;
    float* sx   = sm + MS_OFF;      // aliased: only used before GEMM
    const int tid = threadIdx.x;
    const int b = blockIdx.x;

    // stage x[b] (600 floats)
    for (int i = tid; i < 150; i += 256)
        ((float4*)sx)[i] = ((const float4*)(x + (size_t)b * 600))[i];
    __syncthreads();

    // ---- conv1x1 + GroupNorm(16 groups), thread = channel ----
    {
        const int c = tid;
        float wr[10];
        #pragma unroll
        for (int i = 0; i < 10; ++i) wr[i] = Wc[c * 10 + i];
        const float bb = bc[c];
        float s1 = 0.f, s2 = 0.f;
        float* vrow = vTf + c * VT_STRIDE;
        #pragma unroll 4
        for (int t = 0; t < 60; ++t) {
            const float* xr = sx + t * 10;
            float h = bb;
            #pragma unroll
            for (int i = 0; i < 10; ++i) h = fmaf(wr[i], xr[i], h);
            vrow[t] = h; s1 += h; s2 = fmaf(h, h, s2);
        }
        #pragma unroll
        for (int o = 8; o; o >>= 1) {
            s1 += __shfl_xor_sync(0xffffffffu, s1, o);
            s2 += __shfl_xor_sync(0xffffffffu, s2, o);
        }
        float mean = s1 * (1.f / 960.f);
        float var = s2 * (1.f / 960.f) - mean * mean;
        float sc = ginw[c] * rsqrtf(var + EPSF);
        float sh = ginb[c] - mean * sc;
        #pragma unroll 4
        for (int t = 0; t < 60; ++t) vrow[t] = fmaf(vrow[t], sc, sh);
        #pragma unroll
        for (int t = 60; t < 66; ++t) vrow[t] = 0.f;
    }
    __syncthreads();   // vT ready; sx fully consumed before Ms/Pch writes

    const int e0 = (b * 13) >> 10;
    const int e12 = (b * 13 + 12) >> 10;
    const int nchunks = (e0 == e12) ? 2 : 4;
    const int w = tid >> 5;
    const int lane = tid & 31;

    // staging coords: two float4 units per thread per 16-c step
    const int q1 = tid + 256;
    const int c_0 = tid >> 5,  s_0 = (tid >> 2) & 7, f_0 = tid & 3;
    const int c_1 = q1 >> 5,   s_1 = (q1 >> 2) & 7,  f_1 = q1 & 3;
    const unsigned pchbase = (unsigned)__cvta_generic_to_shared(Pch);
    const unsigned dst0 = pchbase + (unsigned)((c_0 * 128 + s_0 * 16 + f_0 * 4) * 4);
    const unsigned dst1 = pchbase + (unsigned)((c_1 * 128 + s_1 * 16 + f_1 * 4) * 4);

    for (int chunk = 0; chunk < nchunks; ++chunk) {
        const int S0 = chunk * 8 + s_0;
        const int S1 = chunk * 8 + s_1;
        const int mm0 = (S0 < 16) ? (S0 * 13 + e0) : ((S0 - 16) * 13 + e0 + 1);
        const int mm1 = (S1 < 16) ? (S1 * 13 + e0) : ((S1 - 16) * 13 + e0 + 1);
        const float* src0 = g_P + (size_t)c_0 * 3328 + mm0 * 16 + f_0 * 4;
        const float* src1 = g_P + (size_t)c_1 * 3328 + mm1 * 16 + f_1 * 4;

        ull acc[4][4];
        #pragma unroll
        for (int i = 0; i < 4; ++i)
            #pragma unroll
            for (int j = 0; j < 4; ++j) acc[i][j] = 0ull;

        // prologue: prefetch step 0
        cpa16(dst0, src0);
        cpa16(dst1, src1);
        cpa_commit();

        for (int step = 0; step < 16; ++step) {
            cpa_wait0();
            __syncthreads();
            if (step + 1 < 16) {
                unsigned boff = ((step + 1) & 1) * 8192u;
                cpa16(dst0 + boff, src0 + (size_t)(step + 1) * 53248);
                cpa16(dst1 + boff, src1 + (size_t)(step + 1) * 53248);
                cpa_commit();
            }
            const float* Pbuf = Pch + (step & 1) * 2048;
            const int c0 = step * 16;
            #pragma unroll
            for (int kk = 0; kk < 16; ++kk) {
                const float* vb = vTf + (c0 + kk) * VT_STRIDE + w * 8;
                ull v0 = *(const ull*)(vb);
                ull v1 = *(const ull*)(vb + 2);
                ull v2 = *(const ull*)(vb + 4);
                ull v3 = *(const ull*)(vb + 6);
                float4 pp = *(const float4*)(Pbuf + kk * 128 + lane * 4);
                ull p0 = dup2(pp.x), p1 = dup2(pp.y), p2 = dup2(pp.z), p3 = dup2(pp.w);
                acc[0][0] = fma2(v0, p0, acc[0][0]);
                acc[0][1] = fma2(v0, p1, acc[0][1]);
                acc[0][2] = fma2(v0, p2, acc[0][2]);
                acc[0][3] = fma2(v0, p3, acc[0][3]);
                acc[1][0] = fma2(v1, p0, acc[1][0]);
                acc[1][1] = fma2(v1, p1, acc[1][1]);
                acc[1][2] = fma2(v1, p2, acc[1][2]);
                acc[1][3] = fma2(v1, p3, acc[1][3]);
                acc[2][0] = fma2(v2, p0, acc[2][0]);
                acc[2][1] = fma2(v2, p1, acc[2][1]);
                acc[2][2] = fma2(v2, p2, acc[2][2]);
                acc[2][3] = fma2(v2, p3, acc[2][3]);
                acc[3][0] = fma2(v3, p0, acc[3][0]);
                acc[3][1] = fma2(v3, p1, acc[3][1]);
                acc[3][2] = fma2(v3, p2, acc[3][2]);
                acc[3][3] = fma2(v3, p3, acc[3][3]);
            }
        }

        // write Ms (rows = t-pairs, 256-float rows), chunk-local cols 0..127
        #pragma unroll
        for (int i = 0; i < 4; ++i) {
            int tp = w * 4 + i;
            *(ulonglong2*)(MsF + tp * 256 + lane * 8) = make_ulonglong2(acc[i][0], acc[i][1]);
            *(ulonglong2*)(MsF + tp * 256 + lane * 8 + 4) = make_ulonglong2(acc[i][2], acc[i][3]);
        }
        __syncthreads();

        // ---- epilogue for this chunk: warp w owns hk = (chunk&1)*8 + w ----
        const int ec = e0 + (chunk >> 1);
        const int hk = ((chunk & 1) << 3) + w;
        for (int j = 0; j < 13; ++j) {
            int e = (b * 13 + j) >> 10;
            if (e != ec) continue;
            int m = hk * 13 + e;
            int val = j * 240 + lane * 4;
            int t = val / 52;
            int a = (val - t * 52) >> 2;
            float l1 = MsF[2 * ((t >> 1) * 128 + w * 16 + a) + (t & 1)] + g_Pb[m * 16 + a];
            float l2 = -1e30f;
            if (lane < 28) {
                int val2 = val + 128;
                int t2 = val2 / 52;
                int a2 = (val2 - t2 * 52) >> 2;
                l2 = MsF[2 * ((t2 >> 1) * 128 + w * 16 + a2) + (t2 & 1)] + g_Pb[m * 16 + a2];
            }
            float mx = fmaxf(l1, l2);
            #pragma unroll
            for (int o = 16; o; o >>= 1) mx = fmaxf(mx, __shfl_xor_sync(0xffffffffu, mx, o));
            float x1 = __expf(l1 - mx);
            float x2 = (lane < 28) ? __expf(l2 - mx) : 0.f;
            float sum = x1 + x2;
            #pragma unroll
            for (int o = 16; o; o >>= 1) sum += __shfl_xor_sync(0xffffffffu, sum, o);
            float inv = 1.f / sum;
            pbuf[w * 64 + lane] = x1 * inv;
            if (lane < 28) pbuf[w * 64 + 32 + lane] = x2 * inv;
            __syncwarp();
            // AV: lanes 0..15 sum t 0..29, lanes 16..31 sum t 30..59
            int dh = lane & 15;
            int toff = (lane >> 4) * 30;
            const float* vcol = vTf + (hk * 16 + dh) * VT_STRIDE + toff;
            const float* pb = pbuf + w * 64 + toff;
            float a0 = 0.f, a1 = 0.f;
            #pragma unroll
            for (int tt = 0; tt < 15; ++tt) {
                a0 = fmaf(pb[tt], vcol[tt], a0);
                a1 = fmaf(pb[tt + 15], vcol[tt + 15], a1);
            }
            float acv = a0 + a1;
            acv += __shfl_xor_sync(0xffffffffu, acv, 16);
            if (lane < 16) {
                int bq = (b * 13 + j) & 1023;
                g_att[(size_t)((m >> 4) * 1024 + bq) * 256 + ((m & 15) << 4) + dh] = acv;
            }
            __syncwarp();
        }
        __syncthreads();   // Ms/pbuf reads done before next chunk overwrites
    }
}

// ================= MLP + BN + ReLU + GroupNorm + permute =================
// 104 blocks x 128 rows (round-3 proven version, 37.4 us)
#define SO_OFF   0                          // [128][260]
#define SWC_OFF  (128*260)                  // [64][132]
#define SBF_OFF  (SWC_OFF + 64*132)
#define SGW_OFF  (SBF_OFF + 128)
#define SGB_OFF  (SGW_OFF + 128)
#define SMEM_MLP_FLOATS (SGB_OFF + 128)
#define SMEM_MLP_BYTES  (SMEM_MLP_FLOATS * 4)

__global__ void __launch_bounds__(256, 1) k_mlp(const float* __restrict__ gow,
                                                const float* __restrict__ gob,
                                                float* __restrict__ out) {
    extern __shared__ float sm[];
    float* sO  = sm + SO_OFF;
    float* sW  = sm + SWC_OFF;
    float* sBF = sm + SBF_OFF;
    float* sGW = sm + SGW_OFF;
    float* sGB = sm + SGB_OFF;
    const int tid = threadIdx.x;
    const int row0 = blockIdx.x * 128;

    for (int q = tid; q < 8192; q += 256) {
        int row = q >> 6, c4 = q & 63;
        *(float4*)(sO + row * 260 + c4 * 4) =
            *(const float4*)(g_att + (size_t)(row0 + row) * 256 + c4 * 4);
    }
    if (tid < 128) { sBF[tid] = g_bf[tid]; sGW[tid] = gow[tid]; sGB[tid] = gob[tid]; }

    const int rq = tid >> 3;       // 0..31
    const int fg = tid & 7;        // f = 16k + fg*2 + {0,1}
    ull acc[4][8];
    #pragma unroll
    for (int i = 0; i < 4; ++i)
        #pragma unroll
        for (int k = 0; k < 8; ++k) acc[i][k] = 0ull;

    for (int cc = 0; cc < 4; ++cc) {
        __syncthreads();
        for (int q = tid; q < 2048; q += 256) {
            int c = q >> 5, f4 = q & 31;
            *(float4*)(sW + c * 132 + f4 * 4) =
                *(const float4*)(g_W1T + (size_t)(cc * 64 + c) * 128 + f4 * 4);
        }
        __syncthreads();
        #pragma unroll 4
        for (int c = 0; c < 64; ++c) {
            const float* wr = sW + c * 132 + fg * 2;
            ull wv[8];
            #pragma unroll
            for (int k = 0; k < 8; ++k) wv[k] = *(const ull*)(wr + 16 * k);
            int cg = cc * 64 + c;
            #pragma unroll
            for (int i = 0; i < 4; ++i) {
                ull od = dup2(sO[(rq + 32 * i) * 260 + cg]);
                #pragma unroll
                for (int k = 0; k < 8; ++k)
                    acc[i][k] = fma2(od, wv[k], acc[i][k]);
            }
        }
    }

    #pragma unroll
    for (int i = 0; i < 4; ++i) {
        int r = row0 + rq + 32 * i;
        float* orow_out = out + (size_t)((r & 1023) * 13 + (r >> 10)) * 128;
        #pragma unroll
        for (int k = 0; k < 8; ++k) {
            int f = 16 * k + fg * 2;
            float y0 = fmaxf(lo32(acc[i][k]) + sBF[f], 0.f);
            float y1 = fmaxf(hi32(acc[i][k]) + sBF[f + 1], 0.f);
            float s = y0 + y1;
            float s2 = y0 * y0 + y1 * y1;
            s  += __shfl_xor_sync(0xffffffffu, s, 1);
            s2 += __shfl_xor_sync(0xffffffffu, s2, 1);
            s  += __shfl_xor_sync(0xffffffffu, s, 2);
            s2 += __shfl_xor_sync(0xffffffffu, s2, 2);
            float mean = s * 0.125f;
            float var = s2 * 0.125f - mean * mean;
            float sc = rsqrtf(var + EPSF);
            float o0 = (y0 - mean) * sc * sGW[f] + sGB[f];
            float o1 = (y1 - mean) * sc * sGW[f + 1] + sGB[f + 1];
            *(float2*)(orow_out + f) = make_float2(o0, o1);
        }
    }
}

// ================= launch =================
extern "C" void kernel_launch(void* const* d_in, const int* in_sizes, int n_in,
                              void* d_out, int out_size) {
    (void)in_sizes; (void)n_in; (void)out_size;
    const float* x    = (const float*)d_in[0];
    const float* Wc   = (const float*)d_in[1];
    const float* bc   = (const float*)d_in[2];
    const float* ginw = (const float*)d_in[3];
    const float* ginb = (const float*)d_in[4];
    const float* Q    = (const float*)d_in[5];
    const float* Wk   = (const float*)d_in[6];
    const float* bk   = (const float*)d_in[7];
    const float* W1   = (const float*)d_in[8];
    const float* b1   = (const float*)d_in[9];
    const float* bnw  = (const float*)d_in[10];
    const float* bnb  = (const float*)d_in[11];
    const float* bnrm = (const float*)d_in[12];
    const float* bnrv = (const float*)d_in[13];
    const float* gow  = (const float*)d_in[14];
    const float* gob  = (const float*)d_in[15];
    float* out = (float*)d_out;

    cudaFuncSetAttribute(k_attention, cudaFuncAttributeMaxDynamicSharedMemorySize, SMEM_ATT_BYTES);
    cudaFuncSetAttribute(k_mlp, cudaFuncAttributeMaxDynamicSharedMemorySize, SMEM_MLP_BYTES);

    k_precompP<<<208, 256>>>(Q, Wk, bk);                       // launch 1
    k_foldW1<<<128, 256>>>(W1, b1, bnw, bnb, bnrm, bnrv);      // launch 2
    k_nop<<<1, 32>>>();                                        // launch 3
    k_attention<<<1024, 256, SMEM_ATT_BYTES>>>(x, Wc, bc, ginw, ginb);  // launch 4 (ncu target)
    k_mlp<<<104, 256, SMEM_MLP_BYTES>>>(gow, gob, out);        // launch 5
}

// round 8
// speedup vs baseline: 2.0415x; 1.0925x over previous
#include <cuda_runtime.h>
#include <cuda_bf16.h>
#include <cstdint>

typedef unsigned long long ull;

#define EPSF 1e-5f

// ---------------- scratch ----------------
__device__ float g_P[(size_t)256 * 208 * 16];   // [c][m][a16], 0.5 folded
__device__ float g_Pb[208 * 16];                // [m][a16], 0.5 folded
__device__ float g_W1T[256 * 128];              // [c][f], BN-scale folded
__device__ float g_bf[128];                     // folded bias
__device__ float g_att[(size_t)13312 * 256];    // attention out, row = a*1024 + b

// ---------------- helpers ----------------
__device__ __forceinline__ ull fma2(ull a, ull b, ull c) {
    ull d;
    asm("fma.rn.f32x2 %0, %1, %2, %3;" : "=l"(d) : "l"(a), "l"(b), "l"(c));
    return d;
}
__device__ __forceinline__ ull dup2(float v) {
    ull d; unsigned r = __float_as_uint(v);
    asm("mov.b64 %0, {%1, %1};" : "=l"(d) : "r"(r));
    return d;
}
__device__ __forceinline__ float lo32(ull a) { return __uint_as_float((unsigned)(a & 0xffffffffull)); }
__device__ __forceinline__ float hi32(ull a) { return __uint_as_float((unsigned)(a >> 32)); }

__device__ __forceinline__ void cpa16(unsigned dst, const void* src) {
    asm volatile("cp.async.ca.shared.global [%0], [%1], 16;" :: "r"(dst), "l"(src));
}
__device__ __forceinline__ void cpa_commit() {
    asm volatile("cp.async.commit_group;" ::: "memory");
}
__device__ __forceinline__ void cpa_wait0() {
    asm volatile("cp.async.wait_group 0;" ::: "memory");
}

// ================= dummy (ncu capture alignment: capture = 4th launch) =====
__global__ void k_nop() {}

// ================= fold Q into Wk =================
__global__ void k_precompP(const float* __restrict__ Q,
                           const float* __restrict__ Wk,
                           const float* __restrict__ bk) {
    int m = blockIdx.x;            // 0..207
    int c = threadIdx.x;           // 0..255
    int hk = m / 13;
    const float* qp = Q + m * 4;
    float q0 = qp[0], q1 = qp[1], q2 = qp[2], q3 = qp[3];
    float* dst = g_P + (size_t)c * 3328 + m * 16;
    #pragma unroll
    for (int a = 0; a < 13; ++a) {
        const float* w = Wk + (size_t)(a * 64 + hk * 4) * 256 + c;
        float s = q0 * w[0] + q1 * w[256] + q2 * w[512] + q3 * w[768];
        dst[a] = 0.5f * s;
    }
    dst[13] = dst[14] = dst[15] = 0.f;
    if (c < 16) {
        float v = 0.f;
        if (c < 13) {
            const float* bb = bk + c * 64 + hk * 4;
            v = 0.5f * (q0 * bb[0] + q1 * bb[1] + q2 * bb[2] + q3 * bb[3]);
        }
        g_Pb[m * 16 + c] = v;
    }
}

// ================= fold BN into W1, transpose =================
__global__ void k_foldW1(const float* __restrict__ W1, const float* __restrict__ b1,
                         const float* __restrict__ bnw, const float* __restrict__ bnb,
                         const float* __restrict__ bnrm, const float* __restrict__ bnrv) {
    int f = blockIdx.x;    // 0..127
    int c = threadIdx.x;   // 0..255
    float s = bnw[f] * rsqrtf(bnrv[f] + EPSF);
    g_W1T[c * 128 + f] = W1[f * 256 + c] * s;
    if (c == 0) g_bf[f] = b1[f] * s + bnb[f] - bnrm[f] * s;
}

// ================= fused conv + GN + logits + softmax + AV =================
// smem (floats): vT [256][66] | Pch 2 bufs x 8c x 128 | Ms 32 rows x 256
// pbuf aliased onto Ms rows 30-31; sx aliased onto Ms (pre-GEMM only).
// Total = 16896 + 2048 + 8192 = 27136 floats = 108,544 B -> 2 CTAs/SM (14 KB slack)
#define VT_STRIDE 66
#define VT_OFF   0                               // 16896
#define PCH_OFF  (VT_OFF + 256*VT_STRIDE)        // 2048
#define MS_OFF   (PCH_OFF + 2048)                // 8192
#define PB_OFF   (MS_OFF + 30*256)               // rows 30-31
#define SMEM_ATT_FLOATS (MS_OFF + 32*256)        // 27136
#define SMEM_ATT_BYTES  (SMEM_ATT_FLOATS * 4)    // 108,544 B

__global__ void __launch_bounds__(256, 2) k_attention(
    const float* __restrict__ x, const float* __restrict__ Wc,
    const float* __restrict__ bc, const float* __restrict__ ginw,
    const float* __restrict__ ginb) {
    extern __shared__ float sm[];
    float* vTf  = sm + VT_OFF;
    float* Pch  = sm + PCH_OFF;
    float* MsF  = sm + MS_OFF;
    float* pbuf = sm + PB_OFF;
    float* sx   = sm + MS_OFF;      // aliased: only used before GEMM
    const int tid = threadIdx.x;
    const int b = blockIdx.x;

    // stage x[b] (600 floats)
    for (int i = tid; i < 150; i += 256)
        ((float4*)sx)[i] = ((const float4*)(x + (size_t)b * 600))[i];
    __syncthreads();

    // ---- conv1x1 + GroupNorm(16 groups), thread = channel ----
    {
        const int c = tid;
        float wr[10];
        #pragma unroll
        for (int i = 0; i < 10; ++i) wr[i] = Wc[c * 10 + i];
        const float bb = bc[c];
        float s1 = 0.f, s2 = 0.f;
        float* vrow = vTf + c * VT_STRIDE;
        #pragma unroll 4
        for (int t = 0; t < 60; ++t) {
            const float* xr = sx + t * 10;
            float h = bb;
            #pragma unroll
            for (int i = 0; i < 10; ++i) h = fmaf(wr[i], xr[i], h);
            vrow[t] = h; s1 += h; s2 = fmaf(h, h, s2);
        }
        #pragma unroll
        for (int o = 8; o; o >>= 1) {
            s1 += __shfl_xor_sync(0xffffffffu, s1, o);
            s2 += __shfl_xor_sync(0xffffffffu, s2, o);
        }
        float mean = s1 * (1.f / 960.f);
        float var = s2 * (1.f / 960.f) - mean * mean;
        float sc = ginw[c] * rsqrtf(var + EPSF);
        float sh = ginb[c] - mean * sc;
        #pragma unroll 4
        for (int t = 0; t < 60; ++t) vrow[t] = fmaf(vrow[t], sc, sh);
        #pragma unroll
        for (int t = 60; t < 66; ++t) vrow[t] = 0.f;
    }
    __syncthreads();   // vT ready; sx fully consumed before Ms/Pch writes

    const int e0 = (b * 13) >> 10;
    const int e12 = (b * 13 + 12) >> 10;
    const int nchunks = (e0 == e12) ? 2 : 4;
    const int w = tid >> 5;
    const int lane = tid & 31;

    // staging coords: one float4 per thread per 8-c step
    const int sc_ = tid >> 5;          // c within step (0..7)
    const int ss_ = (tid >> 2) & 7;    // col group (16 cols)
    const int sf_ = tid & 3;           // float4 within group
    const unsigned pch_b = (unsigned)__cvta_generic_to_shared(Pch) +
                           (unsigned)((sc_ * 128 + ss_ * 16 + sf_ * 4) * 4);

    for (int chunk = 0; chunk < nchunks; ++chunk) {
        const int S = chunk * 8 + ss_;
        const int mm = (S < 16) ? (S * 13 + e0) : ((S - 16) * 13 + e0 + 1);
        const float* src0 = g_P + (size_t)sc_ * 3328 + mm * 16 + sf_ * 4;

        ull acc[4][4];
        #pragma unroll
        for (int i = 0; i < 4; ++i)
            #pragma unroll
            for (int j = 0; j < 4; ++j) acc[i][j] = 0ull;

        // prologue: prefetch step 0
        cpa16(pch_b, src0);
        cpa_commit();

        for (int step = 0; step < 32; ++step) {
            cpa_wait0();
            __syncthreads();
            if (step + 1 < 32) {
                cpa16(pch_b + ((step + 1) & 1) * 4096u,
                      src0 + (size_t)(step + 1) * 26624);
                cpa_commit();
            }
            const float* Pbuf = Pch + (step & 1) * 1024;
            const int c0 = step * 8;
            #pragma unroll
            for (int kk = 0; kk < 8; ++kk) {
                const float* vb = vTf + (c0 + kk) * VT_STRIDE + w * 8;
                ull v0 = *(const ull*)(vb);
                ull v1 = *(const ull*)(vb + 2);
                ull v2 = *(const ull*)(vb + 4);
                ull v3 = *(const ull*)(vb + 6);
                float4 pp = *(const float4*)(Pbuf + kk * 128 + lane * 4);
                ull p0 = dup2(pp.x), p1 = dup2(pp.y), p2 = dup2(pp.z), p3 = dup2(pp.w);
                acc[0][0] = fma2(v0, p0, acc[0][0]);
                acc[0][1] = fma2(v0, p1, acc[0][1]);
                acc[0][2] = fma2(v0, p2, acc[0][2]);
                acc[0][3] = fma2(v0, p3, acc[0][3]);
                acc[1][0] = fma2(v1, p0, acc[1][0]);
                acc[1][1] = fma2(v1, p1, acc[1][1]);
                acc[1][2] = fma2(v1, p2, acc[1][2]);
                acc[1][3] = fma2(v1, p3, acc[1][3]);
                acc[2][0] = fma2(v2, p0, acc[2][0]);
                acc[2][1] = fma2(v2, p1, acc[2][1]);
                acc[2][2] = fma2(v2, p2, acc[2][2]);
                acc[2][3] = fma2(v2, p3, acc[2][3]);
                acc[3][0] = fma2(v3, p0, acc[3][0]);
                acc[3][1] = fma2(v3, p1, acc[3][1]);
                acc[3][2] = fma2(v3, p2, acc[3][2]);
                acc[3][3] = fma2(v3, p3, acc[3][3]);
            }
        }

        // write Ms (rows = t-pairs, 256-float rows), chunk-local cols 0..127
        #pragma unroll
        for (int i = 0; i < 4; ++i) {
            int tp = w * 4 + i;
            *(ulonglong2*)(MsF + tp * 256 + lane * 8) = make_ulonglong2(acc[i][0], acc[i][1]);
            *(ulonglong2*)(MsF + tp * 256 + lane * 8 + 4) = make_ulonglong2(acc[i][2], acc[i][3]);
        }
        __syncthreads();

        // ---- epilogue for this chunk: warp w owns hk = (chunk&1)*8 + w ----
        const int ec = e0 + (chunk >> 1);
        const int hk = ((chunk & 1) << 3) + w;
        for (int j = 0; j < 13; ++j) {
            int e = (b * 13 + j) >> 10;
            if (e != ec) continue;
            int m = hk * 13 + e;
            int val = j * 240 + lane * 4;
            int t = val / 52;
            int a = (val - t * 52) >> 2;
            float l1 = MsF[2 * ((t >> 1) * 128 + w * 16 + a) + (t & 1)] + g_Pb[m * 16 + a];
            float l2 = -1e30f;
            if (lane < 28) {
                int val2 = val + 128;
                int t2 = val2 / 52;
                int a2 = (val2 - t2 * 52) >> 2;
                l2 = MsF[2 * ((t2 >> 1) * 128 + w * 16 + a2) + (t2 & 1)] + g_Pb[m * 16 + a2];
            }
            float mx = fmaxf(l1, l2);
            #pragma unroll
            for (int o = 16; o; o >>= 1) mx = fmaxf(mx, __shfl_xor_sync(0xffffffffu, mx, o));
            float x1 = __expf(l1 - mx);
            float x2 = (lane < 28) ? __expf(l2 - mx) : 0.f;
            float sum = x1 + x2;
            #pragma unroll
            for (int o = 16; o; o >>= 1) sum += __shfl_xor_sync(0xffffffffu, sum, o);
            float inv = 1.f / sum;
            pbuf[w * 64 + lane] = x1 * inv;
            if (lane < 28) pbuf[w * 64 + 32 + lane] = x2 * inv;
            __syncwarp();
            // AV: lanes 0..15 sum t 0..29, lanes 16..31 sum t 30..59
            int dh = lane & 15;
            int toff = (lane >> 4) * 30;
            const float* vcol = vTf + (hk * 16 + dh) * VT_STRIDE + toff;
            const float* pb = pbuf + w * 64 + toff;
            float a0 = 0.f, a1 = 0.f;
            #pragma unroll
            for (int tt = 0; tt < 15; ++tt) {
                a0 = fmaf(pb[tt], vcol[tt], a0);
                a1 = fmaf(pb[tt + 15], vcol[tt + 15], a1);
            }
            float acv = a0 + a1;
            acv += __shfl_xor_sync(0xffffffffu, acv, 16);
            if (lane < 16) {
                int bq = (b * 13 + j) & 1023;
                g_att[(size_t)((m >> 4) * 1024 + bq) * 256 + ((m & 15) << 4) + dh] = acv;
            }
            __syncwarp();
        }
        __syncthreads();   // Ms/pbuf reads done before next chunk overwrites
    }
}

// ================= MLP + BN + ReLU + GroupNorm + permute =================
// 104 blocks x 128 rows (round-3 proven version, 37.4 us)
#define SO_OFF   0                          // [128][260]
#define SWC_OFF  (128*260)                  // [64][132]
#define SBF_OFF  (SWC_OFF + 64*132)
#define SGW_OFF  (SBF_OFF + 128)
#define SGB_OFF  (SGW_OFF + 128)
#define SMEM_MLP_FLOATS (SGB_OFF + 128)
#define SMEM_MLP_BYTES  (SMEM_MLP_FLOATS * 4)

__global__ void __launch_bounds__(256, 1) k_mlp(const float* __restrict__ gow,
                                                const float* __restrict__ gob,
                                                float* __restrict__ out) {
    extern __shared__ float sm[];
    float* sO  = sm + SO_OFF;
    float* sW  = sm + SWC_OFF;
    float* sBF = sm + SBF_OFF;
    float* sGW = sm + SGW_OFF;
    float* sGB = sm + SGB_OFF;
    const int tid = threadIdx.x;
    const int row0 = blockIdx.x * 128;

    for (int q = tid; q < 8192; q += 256) {
        int row = q >> 6, c4 = q & 63;
        *(float4*)(sO + row * 260 + c4 * 4) =
            *(const float4*)(g_att + (size_t)(row0 + row) * 256 + c4 * 4);
    }
    if (tid < 128) { sBF[tid] = g_bf[tid]; sGW[tid] = gow[tid]; sGB[tid] = gob[tid]; }

    const int rq = tid >> 3;       // 0..31
    const int fg = tid & 7;        // f = 16k + fg*2 + {0,1}
    ull acc[4][8];
    #pragma unroll
    for (int i = 0; i < 4; ++i)
        #pragma unroll
        for (int k = 0; k < 8; ++k) acc[i][k] = 0ull;

    for (int cc = 0; cc < 4; ++cc) {
        __syncthreads();
        for (int q = tid; q < 2048; q += 256) {
            int c = q >> 5, f4 = q & 31;
            *(float4*)(sW + c * 132 + f4 * 4) =
                *(const float4*)(g_W1T + (size_t)(cc * 64 + c) * 128 + f4 * 4);
        }
        __syncthreads();
        #pragma unroll 4
        for (int c = 0; c < 64; ++c) {
            const float* wr = sW + c * 132 + fg * 2;
            ull wv[8];
            #pragma unroll
            for (int k = 0; k < 8; ++k) wv[k] = *(const ull*)(wr + 16 * k);
            int cg = cc * 64 + c;
            #pragma unroll
            for (int i = 0; i < 4; ++i) {
                ull od = dup2(sO[(rq + 32 * i) * 260 + cg]);
                #pragma unroll
                for (int k = 0; k < 8; ++k)
                    acc[i][k] = fma2(od, wv[k], acc[i][k]);
            }
        }
    }

    #pragma unroll
    for (int i = 0; i < 4; ++i) {
        int r = row0 + rq + 32 * i;
        float* orow_out = out + (size_t)((r & 1023) * 13 + (r >> 10)) * 128;
        #pragma unroll
        for (int k = 0; k < 8; ++k) {
            int f = 16 * k + fg * 2;
            float y0 = fmaxf(lo32(acc[i][k]) + sBF[f], 0.f);
            float y1 = fmaxf(hi32(acc[i][k]) + sBF[f + 1], 0.f);
            float s = y0 + y1;
            float s2 = y0 * y0 + y1 * y1;
            s  += __shfl_xor_sync(0xffffffffu, s, 1);
            s2 += __shfl_xor_sync(0xffffffffu, s2, 1);
            s  += __shfl_xor_sync(0xffffffffu, s, 2);
            s2 += __shfl_xor_sync(0xffffffffu, s2, 2);
            float mean = s * 0.125f;
            float var = s2 * 0.125f - mean * mean;
            float sc = rsqrtf(var + EPSF);
            float o0 = (y0 - mean) * sc * sGW[f] + sGB[f];
            float o1 = (y1 - mean) * sc * sGW[f + 1] + sGB[f + 1];
            *(float2*)(orow_out + f) = make_float2(o0, o1);
        }
    }
}

// ================= launch =================
extern "C" void kernel_launch(void* const* d_in, const int* in_sizes, int n_in,
                              void* d_out, int out_size) {
    (void)in_sizes; (void)n_in; (void)out_size;
    const float* x    = (const float*)d_in[0];
    const float* Wc   = (const float*)d_in[1];
    const float* bc   = (const float*)d_in[2];
    const float* ginw = (const float*)d_in[3];
    const float* ginb = (const float*)d_in[4];
    const float* Q    = (const float*)d_in[5];
    const float* Wk   = (const float*)d_in[6];
    const float* bk   = (const float*)d_in[7];
    const float* W1   = (const float*)d_in[8];
    const float* b1   = (const float*)d_in[9];
    const float* bnw  = (const float*)d_in[10];
    const float* bnb  = (const float*)d_in[11];
    const float* bnrm = (const float*)d_in[12];
    const float* bnrv = (const float*)d_in[13];
    const float* gow  = (const float*)d_in[14];
    const float* gob  = (const float*)d_in[15];
    float* out = (float*)d_out;

    cudaFuncSetAttribute(k_attention, cudaFuncAttributeMaxDynamicSharedMemorySize, SMEM_ATT_BYTES);
    cudaFuncSetAttribute(k_mlp, cudaFuncAttributeMaxDynamicSharedMemorySize, SMEM_MLP_BYTES);

    k_precompP<<<208, 256>>>(Q, Wk, bk);                       // launch 1
    k_foldW1<<<128, 256>>>(W1, b1, bnw, bnb, bnrm, bnrv);      // launch 2
    k_nop<<<1, 32>>>();                                        // launch 3
    k_attention<<<1024, 256, SMEM_ATT_BYTES>>>(x, Wc, bc, ginw, ginb);  // launch 4 (ncu target)
    k_mlp<<<104, 256, SMEM_MLP_BYTES>>>(gow, gob, out);        // launch 5
}